// round 1
// baseline (speedup 1.0000x reference)
#include <cuda_runtime.h>
#include <cstdint>
#include <math.h>

#define BATCH 2048
#define DM    1024
#define RNUM  64
#define BNUM  16

// scratch: diag_vals = sigmoid(x@Wa) * tanh(x@Wd)   (8 MB)
__device__ float g_dv[BATCH * DM];

#define PACK2(dst, lo, hi) \
    asm("mov.b64 %0, {%1, %2};" : "=l"(dst) : "r"(__float_as_uint(lo)), "r"(__float_as_uint(hi)))
#define UNPK2(lo, hi, src) do { unsigned _a, _b; \
    asm("mov.b64 {%0, %1}, %2;" : "=r"(_a), "=r"(_b) : "l"(src)); \
    (lo) = __uint_as_float(_a); (hi) = __uint_as_float(_b); } while (0)
#define FFMA2(c, a, b) \
    asm("fma.rn.f32x2 %0, %1, %2, %0;" : "+l"(c) : "l"(a), "l"(b))

// ---------------------------------------------------------------------------
// diag kernel: tile M=64 (batch) x N=64 (model cols), K=1024, Kt=32
// computes g_dv = sigmoid(x@Wa) * tanh(x@Wd)
// ---------------------------------------------------------------------------
__global__ __launch_bounds__(256) void diag_kernel(
    const float* __restrict__ x, const float* __restrict__ Wd,
    const float* __restrict__ Wa)
{
    __shared__ float As[32][68];   // transposed: As[k][m]
    __shared__ float Bd[32][64];
    __shared__ float Ba[32][64];
    const int m0 = blockIdx.x * 64, n0 = blockIdx.y * 64;
    const int tid = threadIdx.x;
    const int tx = tid & 15, ty = tid >> 4;    // 16x16 threads, 4x4 micro-tile
    uint64_t accd[4][2] = {}, acca[4][2] = {};

    for (int kt = 0; kt < DM; kt += 32) {
        #pragma unroll
        for (int i = 0; i < 2; i++) {          // A: 64 x 32 = 512 float4
            int v = tid + i * 256;
            int m = v >> 3, k = (v & 7) << 2;
            float4 t = *(const float4*)(x + (m0 + m) * DM + kt + k);
            As[k + 0][m] = t.x; As[k + 1][m] = t.y;
            As[k + 2][m] = t.z; As[k + 3][m] = t.w;
        }
        #pragma unroll
        for (int i = 0; i < 2; i++) {          // B: 32 x 64 each
            int v = tid + i * 256;
            int k = v >> 4, n = (v & 15) << 2;
            *(float4*)&Bd[k][n] = *(const float4*)(Wd + (kt + k) * DM + n0 + n);
            *(float4*)&Ba[k][n] = *(const float4*)(Wa + (kt + k) * DM + n0 + n);
        }
        __syncthreads();
        #pragma unroll
        for (int k = 0; k < 32; k++) {
            float4 a4 = *(const float4*)&As[k][ty * 4];
            float4 bd = *(const float4*)&Bd[k][tx * 4];
            float4 ba = *(const float4*)&Ba[k][tx * 4];
            uint64_t bd2[2], ba2[2];
            PACK2(bd2[0], bd.x, bd.y); PACK2(bd2[1], bd.z, bd.w);
            PACK2(ba2[0], ba.x, ba.y); PACK2(ba2[1], ba.z, ba.w);
            float av[4] = {a4.x, a4.y, a4.z, a4.w};
            #pragma unroll
            for (int i = 0; i < 4; i++) {
                uint64_t a2; PACK2(a2, av[i], av[i]);
                #pragma unroll
                for (int p = 0; p < 2; p++) {
                    FFMA2(accd[i][p], a2, bd2[p]);
                    FFMA2(acca[i][p], a2, ba2[p]);
                }
            }
        }
        __syncthreads();
    }
    #pragma unroll
    for (int i = 0; i < 4; i++) {
        #pragma unroll
        for (int p = 0; p < 2; p++) {
            float d0, d1, a0, a1;
            UNPK2(d0, d1, accd[i][p]);
            UNPK2(a0, a1, acca[i][p]);
            int m = m0 + ty * 4 + i;
            int n = n0 + tx * 4 + p * 2;
            float s0 = 1.0f / (1.0f + expf(-a0));
            float s1 = 1.0f / (1.0f + expf(-a1));
            g_dv[m * DM + n + 0] = s0 * tanhf(d0);
            g_dv[m * DM + n + 1] = s1 * tanhf(d1);
        }
    }
}

// ---------------------------------------------------------------------------
// perm kernel: tile M=64 (batch) x N=256 (one r block), K=1024, Kt=16
// fused epilogue: sinkhorn(5) -> argmax -> hard permute of h -> * diag -> out
// ---------------------------------------------------------------------------
#define CSTR 260
#define SMEM_FLOATS (64 * CSTR + 16 * 68 + 16 * 256)

__global__ __launch_bounds__(256, 2) void perm_kernel(
    const float* __restrict__ x, const float* __restrict__ Wp,
    const float* __restrict__ h, float* __restrict__ out)
{
    extern __shared__ float sm[];
    float* Csm = sm;                      // 64 * 260
    float* As  = sm + 64 * CSTR;          // 16 * 68 (transposed)
    float* Bs  = As + 16 * 68;            // 16 * 256

    const int m0  = blockIdx.x * 64;
    const int r   = blockIdx.y;
    const int tid = threadIdx.x;
    const int tm  = tid >> 5;             // 0..7  (8 rows each)
    const int tn  = tid & 31;             // cols tn*4..+4 and 128+tn*4..+4

    uint64_t acc[8][4] = {};

    const int am = tid >> 2, ak = (tid & 3) << 2;
    float4 pa;
    float4 pb[4];
    // prologue prefetch
    pa = *(const float4*)(x + (m0 + am) * DM + ak);
    #pragma unroll
    for (int i = 0; i < 4; i++) {
        int v = tid + i * 256; int k = v >> 6, n = (v & 63) << 2;
        pb[i] = *(const float4*)(Wp + k * (RNUM * 256) + r * 256 + n);
    }

    for (int kt = 0; kt < DM; kt += 16) {
        // commit prefetched tile to smem
        As[(ak + 0) * 68 + am] = pa.x; As[(ak + 1) * 68 + am] = pa.y;
        As[(ak + 2) * 68 + am] = pa.z; As[(ak + 3) * 68 + am] = pa.w;
        #pragma unroll
        for (int i = 0; i < 4; i++) {
            int v = tid + i * 256; int k = v >> 6, n = (v & 63) << 2;
            *(float4*)&Bs[k * 256 + n] = pb[i];
        }
        __syncthreads();
        if (kt + 16 < DM) {                 // prefetch next tile
            pa = *(const float4*)(x + (m0 + am) * DM + kt + 16 + ak);
            #pragma unroll
            for (int i = 0; i < 4; i++) {
                int v = tid + i * 256; int k = v >> 6, n = (v & 63) << 2;
                pb[i] = *(const float4*)(Wp + (kt + 16 + k) * (RNUM * 256) + r * 256 + n);
            }
        }
        #pragma unroll
        for (int k = 0; k < 16; k++) {
            float4 a0 = *(const float4*)&As[k * 68 + tm * 8];
            float4 a1 = *(const float4*)&As[k * 68 + tm * 8 + 4];
            float4 b0 = *(const float4*)&Bs[k * 256 + tn * 4];
            float4 b1 = *(const float4*)&Bs[k * 256 + 128 + tn * 4];
            uint64_t b2[4];
            PACK2(b2[0], b0.x, b0.y); PACK2(b2[1], b0.z, b0.w);
            PACK2(b2[2], b1.x, b1.y); PACK2(b2[3], b1.z, b1.w);
            float av[8] = {a0.x, a0.y, a0.z, a0.w, a1.x, a1.y, a1.z, a1.w};
            #pragma unroll
            for (int i = 0; i < 8; i++) {
                uint64_t a2; PACK2(a2, av[i], av[i]);
                #pragma unroll
                for (int p = 0; p < 4; p++) FFMA2(acc[i][p], a2, b2[p]);
            }
        }
        __syncthreads();
    }

    // stage C tile in smem
    #pragma unroll
    for (int i = 0; i < 8; i++) {
        int m = tm * 8 + i;
        float l0, h0, l1, h1;
        UNPK2(l0, h0, acc[i][0]); UNPK2(l1, h1, acc[i][1]);
        *(float4*)&Csm[m * CSTR + tn * 4] = make_float4(l0, h0, l1, h1);
        UNPK2(l0, h0, acc[i][2]); UNPK2(l1, h1, acc[i][3]);
        *(float4*)&Csm[m * CSTR + 128 + tn * 4] = make_float4(l0, h0, l1, h1);
    }
    __syncthreads();

    // ---- sinkhorn + argmax + permute epilogue ----
    // each warp processes 2 blocks (lanes 0-15 -> block A, 16-31 -> block B);
    // lane j owns column j (16 rows in registers)
    const int w = tid >> 5, lane = tid & 31;
    const int j = lane & 15, half = lane >> 4, gb = half << 4;
    const unsigned FULL = 0xffffffffu;

    #pragma unroll 1
    for (int pass = 0; pass < 4; pass++) {
        int m = pass * 16 + w * 2 + half;   // batch row within tile (block id)
        float la[16];
        #pragma unroll
        for (int i = 0; i < 16; i++)
            la[i] = 2.0f * Csm[m * CSTR + i * 16 + j];   // /TAU (TAU=0.5)

        #pragma unroll 1
        for (int it = 0; it < 5; it++) {
            // row normalization: logsumexp over columns (across 16 lanes)
            #pragma unroll
            for (int i = 0; i < 16; i++) {
                float mx = la[i];
                mx = fmaxf(mx, __shfl_xor_sync(FULL, mx, 1));
                mx = fmaxf(mx, __shfl_xor_sync(FULL, mx, 2));
                mx = fmaxf(mx, __shfl_xor_sync(FULL, mx, 4));
                mx = fmaxf(mx, __shfl_xor_sync(FULL, mx, 8));
                float e = __expf(la[i] - mx);
                e += __shfl_xor_sync(FULL, e, 1);
                e += __shfl_xor_sync(FULL, e, 2);
                e += __shfl_xor_sync(FULL, e, 4);
                e += __shfl_xor_sync(FULL, e, 8);
                la[i] -= mx + __logf(e);
            }
            // column normalization: logsumexp over rows (local)
            float mx = la[0];
            #pragma unroll
            for (int i = 1; i < 16; i++) mx = fmaxf(mx, la[i]);
            float s = 0.f;
            #pragma unroll
            for (int i = 0; i < 16; i++) s += __expf(la[i] - mx);
            float sub = mx + __logf(s);
            #pragma unroll
            for (int i = 0; i < 16; i++) la[i] -= sub;
        }

        // argmax over rows (first-max rule matches jnp.argmax)
        int best = 0; float bv = la[0];
        #pragma unroll
        for (int i = 1; i < 16; i++)
            if (la[i] > bv) { bv = la[i]; best = i; }

        int bg = m0 + m;
        float hv = h[bg * DM + r * 16 + j];

        // h_permuted[i] = sum_{j : best_j == i} h_j   (lane's j acts as row i)
        float hp = 0.f;
        #pragma unroll
        for (int jj = 0; jj < 16; jj++) {
            int   ib = __shfl_sync(FULL, best, gb + jj);
            float hj = __shfl_sync(FULL, hv,   gb + jj);
            if (ib == j) hp += hj;
        }
        int oi = bg * DM + r * 16 + j;
        out[oi] = g_dv[oi] * hp;
    }
}

// ---------------------------------------------------------------------------
extern "C" void kernel_launch(void* const* d_in, const int* in_sizes, int n_in,
                              void* d_out, int out_size)
{
    const float* x  = (const float*)d_in[0];
    const float* h  = (const float*)d_in[1];
    const float* Wp = (const float*)d_in[2];
    const float* Wd = (const float*)d_in[3];
    const float* Wa = (const float*)d_in[4];
    float* out = (float*)d_out;

    cudaFuncSetAttribute(perm_kernel,
                         cudaFuncAttributeMaxDynamicSharedMemorySize,
                         SMEM_FLOATS * (int)sizeof(float));

    diag_kernel<<<dim3(BATCH / 64, DM / 64), 256>>>(x, Wd, Wa);
    perm_kernel<<<dim3(BATCH / 64, RNUM), 256,
                  SMEM_FLOATS * (int)sizeof(float)>>>(x, Wp, h, out);
}